// round 9
// baseline (speedup 1.0000x reference)
#include <cuda_runtime.h>
#include <cuda_fp16.h>
#include <cstdint>
#include <math.h>

// Problem constants
#define BB 64
#define PP 196
#define DD 768
#define CC 201
#define KP 5
#define NCLS 200
#define NN (BB*PP)        // 12544
#define JJ (CC*KP)        // 1005
#define JPAD 1024

// Output layout
#define OFF_LOGITS 0
#define SZ_LOGITS  (NN*JJ)
#define OFF_IMG    (OFF_LOGITS + SZ_LOGITS)
#define SZ_IMG     (BB*JJ)
#define OFF_CLS    (OFF_IMG + SZ_IMG)
#define SZ_CLS     (BB*NCLS)
#define OFF_ASGN   (OFF_CLS + SZ_CLS)
#define SZ_ASGN    (NN)
#define OFF_PNEW   (OFF_ASGN + SZ_ASGN)
#define SZ_PNEW    (CC*KP*DD)

// Device scratch
__device__ __align__(16) __half g_pth[NN*DD];     // fp16(A)
__device__ __align__(16) __half g_pt2[NN*DD];     // fp16(Ah + 64*(A-Ah))
__device__ __align__(16) __half g_pnh[JPAD*DD];   // fp16(B)
__device__ __align__(16) __half g_pn2[JPAD*DD];   // fp16(Bh + 64*(B-Bh))
__device__ float g_inv[NN];                       // 1/||rpt_row||
__device__ float g_sw[NCLS*KP];

// ---------------------------------------------------------------------------
// PTX helpers
// ---------------------------------------------------------------------------
__device__ __forceinline__ void ldsm_x4(uint32_t* r, uint32_t addr) {
    asm volatile("ldmatrix.sync.aligned.m8n8.x4.shared.b16 {%0,%1,%2,%3}, [%4];"
                 : "=r"(r[0]), "=r"(r[1]), "=r"(r[2]), "=r"(r[3]) : "r"(addr));
}
__device__ __forceinline__ void mma_fp16(float* d, const uint32_t* a, const uint32_t* b) {
    asm volatile(
        "mma.sync.aligned.m16n8k16.row.col.f32.f16.f16.f32 "
        "{%0,%1,%2,%3}, {%4,%5,%6,%7}, {%8,%9}, {%0,%1,%2,%3};"
        : "+f"(d[0]), "+f"(d[1]), "+f"(d[2]), "+f"(d[3])
        : "r"(a[0]), "r"(a[1]), "r"(a[2]), "r"(a[3]), "r"(b[0]), "r"(b[1]));
}
__device__ __forceinline__ void cpbulk(uint32_t dst, const void* src, uint32_t bytes,
                                       uint32_t mbar) {
    asm volatile(
        "cp.async.bulk.shared::cta.global.mbarrier::complete_tx::bytes [%0], [%1], %2, [%3];"
        :: "r"(dst), "l"(src), "r"(bytes), "r"(mbar) : "memory");
}
__device__ __forceinline__ void mbar_init(uint32_t mbar, uint32_t cnt) {
    asm volatile("mbarrier.init.shared.b64 [%0], %1;" :: "r"(mbar), "r"(cnt) : "memory");
}
__device__ __forceinline__ void mbar_expect(uint32_t mbar, uint32_t bytes) {
    asm volatile("mbarrier.arrive.expect_tx.shared.b64 _, [%0], %1;"
                 :: "r"(mbar), "r"(bytes) : "memory");
}
__device__ __forceinline__ void mbar_wait(uint32_t mbar, uint32_t parity) {
    asm volatile(
        "{\n\t.reg .pred P;\n\t"
        "W_%=:\n\t"
        "mbarrier.try_wait.parity.acquire.cta.shared::cta.b64 P, [%0], %1, 0x989680;\n\t"
        "@P bra.uni D_%=;\n\t"
        "bra.uni W_%=;\n\t"
        "D_%=:\n\t}"
        :: "r"(mbar), "r"(parity) : "memory");
}
__device__ __forceinline__ void fence_async() {
    asm volatile("fence.proxy.async.shared::cta;" ::: "memory");
}

// ---------------------------------------------------------------------------
// Row L2 normalization + fp16 Ootomo split (warp per row)
// ---------------------------------------------------------------------------
__global__ __launch_bounds__(256) void norm_kernel(const float* __restrict__ pt,
                            const float* __restrict__ rpt,
                            const float* __restrict__ proto) {
    const int r = blockIdx.x * 8 + (threadIdx.x >> 5);
    const int lane = threadIdx.x & 31;
    if (r >= 2*NN + JPAD) return;

    if (r < NN) {
        const float* src = pt + (size_t)r*DD;
        float s = 0.0f;
        for (int i = lane; i < DD; i += 32) { float v = src[i]; s += v*v; }
        #pragma unroll
        for (int o = 16; o > 0; o >>= 1) s += __shfl_xor_sync(0xffffffffu, s, o);
        float inv = 1.0f / fmaxf(sqrtf(s), 1e-12f);
        for (int i = lane; i < DD; i += 32) {
            float x = src[i] * inv;
            __half h = __float2half(x);
            float hf = __half2float(h);
            g_pth[(size_t)r*DD + i] = h;
            g_pt2[(size_t)r*DD + i] = __float2half(fmaf(64.0f, x - hf, hf));
        }
    } else if (r < 2*NN) {
        int rr = r - NN;
        const float* src = rpt + (size_t)rr*DD;
        float s = 0.0f;
        for (int i = lane; i < DD; i += 32) { float v = src[i]; s += v*v; }
        #pragma unroll
        for (int o = 16; o > 0; o >>= 1) s += __shfl_xor_sync(0xffffffffu, s, o);
        if (lane == 0) g_inv[rr] = 1.0f / fmaxf(sqrtf(s), 1e-12f);
    } else {
        int j = r - 2*NN;
        if (j >= JJ) {
            __half z = __float2half(0.0f);
            for (int i = lane; i < DD; i += 32) {
                g_pnh[(size_t)j*DD + i] = z;
                g_pn2[(size_t)j*DD + i] = z;
            }
            return;
        }
        const float* src = proto + (size_t)j*DD;
        float s = 0.0f;
        for (int i = lane; i < DD; i += 32) { float v = src[i]; s += v*v; }
        #pragma unroll
        for (int o = 16; o > 0; o >>= 1) s += __shfl_xor_sync(0xffffffffu, s, o);
        float inv = 1.0f / fmaxf(sqrtf(s), 1e-12f);
        for (int i = lane; i < DD; i += 32) {
            float x = src[i] * inv;
            __half h = __float2half(x);
            float hf = __half2float(h);
            g_pnh[(size_t)j*DD + i] = h;
            g_pn2[(size_t)j*DD + i] = __float2half(fmaf(64.0f, x - hf, hf));
        }
    }
}

// ---------------------------------------------------------------------------
// sw = softmax(sa_weights, axis=-1) * K
// ---------------------------------------------------------------------------
__global__ void sw_kernel(const float* __restrict__ sa) {
    int c = blockIdx.x * blockDim.x + threadIdx.x;
    if (c >= NCLS) return;
    float w[KP];
    float m = -1e30f;
    for (int k = 0; k < KP; k++) { w[k] = sa[c*KP+k]; m = fmaxf(m, w[k]); }
    float s = 0.0f;
    for (int k = 0; k < KP; k++) { w[k] = expf(w[k]-m); s += w[k]; }
    for (int k = 0; k < KP; k++) g_sw[c*KP+k] = w[k] / s * 5.0f;
}

// ---------------------------------------------------------------------------
// 2-product fp16 GEMM (Ootomo, product-split warps):  out = P0 + (P1-P0)/64
// Persistent grid=148; 512 threads = 16 warps (8 tiles x 2 products).
// BK=64, 2-stage, loads via cp.async.bulk (128B/row) + mbarrier.
// ---------------------------------------------------------------------------
#define SAS2 72                              // smem row stride (fp16): 64 data + 8 pad
#define ROW_B 144                            // bytes per row
#define ARR_B (128*ROW_B)                    // 18432 per array
#define STAGE2 (4*ARR_B)                     // 73728 per stage
#define MBAR_OFF (2*STAGE2)                  // 147456
#define SMEM_GEMM (MBAR_OFF + 16)
#define STAGE_BYTES (4*128*128)              // 65536 tx bytes per chunk
#define NCHUNK2 (DD/64)                      // 12
#define MTILES (NN/128)                      // 98
#define NTILES (JPAD/128)                    // 8
#define TOTTILES (MTILES*NTILES)             // 784

__global__ __launch_bounds__(512, 1) void gemm_mma_kernel(float* __restrict__ out) {
    extern __shared__ __align__(16) char smem[];
    const uint32_t sb = (uint32_t)__cvta_generic_to_shared(smem);
    const uint32_t mb0 = sb + MBAR_OFF;
    const uint32_t mb1 = sb + MBAR_OFF + 8;

    const int tid  = threadIdx.x;
    const int lane = tid & 31;
    const int wid  = tid >> 5;
    const int p    = wid >> 3;     // product: 0 -> (Ah,Bh), 1 -> (A2,B2)
    const int t    = wid & 7;      // output tile within CTA
    const int wm   = t & 3;        // M 32-block
    const int wn   = t >> 2;       // N 64-block

    const int arow = (lane & 7) + ((lane >> 3) & 1) * 8;
    const int acol = (lane >> 4) * 8;
    const int brow = (lane & 7) + ((lane >> 4) & 1) * 8;
    const int bcol = ((lane >> 3) & 1) * 8;

    const uint32_t offA = (uint32_t)p * ARR_B;
    const uint32_t offB = (uint32_t)(2 + p) * ARR_B;

    // per-thread copy assignment: 512 rows = 4 arrays x 128 rows
    const int carr = tid >> 7;      // 0..3
    const int crow = tid & 127;

    if (tid == 0) { mbar_init(mb0, 1); mbar_init(mb1, 1); }
    fence_async();
    __syncthreads();

    int ph0 = 0, ph1 = 0;

    // issue one chunk's copies into stage s
    auto load_chunk = [&](int bm, int bn, int kt, int s) {
        uint32_t mb = s ? mb1 : mb0;
        if (tid == 0) mbar_expect(mb, STAGE_BYTES);
        uint32_t dst = sb + s*STAGE2 + carr*ARR_B + crow*ROW_B;
        const __half* src;
        if (carr == 0)      src = g_pth + (size_t)(bm + crow)*DD + kt;
        else if (carr == 1) src = g_pt2 + (size_t)(bm + crow)*DD + kt;
        else if (carr == 2) src = g_pnh + (size_t)(bn + crow)*DD + kt;
        else                src = g_pn2 + (size_t)(bn + crow)*DD + kt;
        cpbulk(dst, src, 128, mb);
    };

    for (int tile = blockIdx.x; tile < TOTTILES; tile += gridDim.x) {
        const int bm = (tile / NTILES) * 128;
        const int bn = (tile % NTILES) * 128;

        float acc[2][8][4];
        #pragma unroll
        for (int i = 0; i < 2; i++)
            #pragma unroll
            for (int j = 0; j < 8; j++)
                #pragma unroll
                for (int q = 0; q < 4; q++) acc[i][j][q] = 0.0f;

        load_chunk(bm, bn, 0, 0);
        load_chunk(bm, bn, 64, 1);

        for (int i = 0; i < NCHUNK2; i++) {
            const int s = i & 1;
            if (s == 0) { mbar_wait(mb0, ph0); ph0 ^= 1; }
            else        { mbar_wait(mb1, ph1); ph1 ^= 1; }

            const uint32_t aA = sb + s*STAGE2 + offA;
            const uint32_t aB = sb + s*STAGE2 + offB;

            #pragma unroll
            for (int ks = 0; ks < 64; ks += 16) {
                uint32_t af[2][4];
                #pragma unroll
                for (int mi = 0; mi < 2; mi++) {
                    uint32_t off = (uint32_t)((wm*32 + mi*16 + arow)*SAS2 + ks + acol) * 2;
                    ldsm_x4(af[mi], aA + off);
                }
                #pragma unroll
                for (int nb = 0; nb < 4; nb++) {
                    uint32_t bf[4];
                    uint32_t off = (uint32_t)((wn*64 + nb*16 + brow)*SAS2 + ks + bcol) * 2;
                    ldsm_x4(bf, aB + off);
                    #pragma unroll
                    for (int mi = 0; mi < 2; mi++) {
                        mma_fp16(acc[mi][nb*2+0], af[mi], bf+0);
                        mma_fp16(acc[mi][nb*2+1], af[mi], bf+2);
                    }
                }
            }
            __syncthreads();   // all warps done reading stage s
            if (i + 2 < NCHUNK2) load_chunk(bm, bn, (i+2)*64, s);
        }

        // epilogue: P1 warps stage to smem; P0 warps combine + store
        float* xbuf = (float*)smem;     // 8 tiles x 2048 floats = 64KB < STAGE2*2
        if (p == 1) {
            float* tb = xbuf + t*2048;
            #pragma unroll
            for (int mi = 0; mi < 2; mi++)
                #pragma unroll
                for (int nf = 0; nf < 8; nf++)
                    #pragma unroll
                    for (int q = 0; q < 4; q++) {
                        int row = mi*16 + (lane >> 2) + (q >> 1)*8;
                        int col = nf*8 + (lane & 3)*2 + (q & 1);
                        tb[row*64 + col] = acc[mi][nf][q];
                    }
        }
        __syncthreads();
        if (p == 0) {
            const float* tb = xbuf + t*2048;
            #pragma unroll
            for (int mi = 0; mi < 2; mi++)
                #pragma unroll
                for (int nf = 0; nf < 8; nf++)
                    #pragma unroll
                    for (int q = 0; q < 4; q++) {
                        int rloc = mi*16 + (lane >> 2) + (q >> 1)*8;
                        int cloc = nf*8 + (lane & 3)*2 + (q & 1);
                        int col = bn + wn*64 + cloc;
                        if (col < JJ) {
                            float p0 = acc[mi][nf][q];
                            float p1 = tb[rloc*64 + cloc];
                            out[(size_t)(bm + wm*32 + rloc)*JJ + col] =
                                p0 + (p1 - p0) * 0.015625f;
                        }
                    }
        }
        __syncthreads();      // epilogue reads/writes done
        fence_async();        // order generic xbuf writes before async bulk writes
    }
}

// ---------------------------------------------------------------------------
// image_logits[b, j] = max_p logits[b, p, j]
// ---------------------------------------------------------------------------
__global__ void imgmax_kernel(const float* __restrict__ logits, float* __restrict__ img) {
    int t = blockIdx.x * blockDim.x + threadIdx.x;
    if (t >= BB*JJ) return;
    int b = t / JJ, j = t % JJ;
    const float* p = logits + (size_t)b*PP*JJ + j;
    float m = -1e30f;
    for (int i = 0; i < PP; i++) m = fmaxf(m, p[(size_t)i*JJ]);
    img[(size_t)b*JJ + j] = m;
}

// ---------------------------------------------------------------------------
// class_logits[b, c] = sum_k img[b, c, k]*sw[c, k] / TEMP
// ---------------------------------------------------------------------------
__global__ void cls_kernel(const float* __restrict__ img, float* __restrict__ cls) {
    int t = blockIdx.x * blockDim.x + threadIdx.x;
    if (t >= BB*NCLS) return;
    int b = t / NCLS, c = t % NCLS;
    float s = 0.0f;
    #pragma unroll
    for (int k = 0; k < KP; k++) s += img[(size_t)b*JJ + c*KP + k] * g_sw[c*KP+k];
    cls[t] = s / 0.2f;
}

// ---------------------------------------------------------------------------
// Per-class: deterministic compaction + Sinkhorn + assignment + P_new
// ---------------------------------------------------------------------------
#define MAXN 1024
__global__ __launch_bounds__(256) void sinkhorn_kernel(
        const float* __restrict__ logits, const int* __restrict__ labels,
        const float* __restrict__ proto, const float* __restrict__ rpt,
        float* __restrict__ assign, float* __restrict__ pnew) {
    const int c = blockIdx.x;
    const int tid = threadIdx.x;
    const int lane = tid & 31, w = tid >> 5;

    __shared__ int   s_idx[MAXN];
    __shared__ float Q[KP][MAXN];
    __shared__ float red[256];
    __shared__ int   warp_cnt[8], warp_off[8];
    __shared__ int   s_n;

    if (tid == 0) s_n = 0;
    __syncthreads();

    for (int base = 0; base < NN; base += 256) {
        int n = base + tid;
        bool p = (labels[n] == c);
        unsigned bal = __ballot_sync(0xffffffffu, p);
        if (lane == 0) warp_cnt[w] = __popc(bal);
        __syncthreads();
        if (tid == 0) {
            int s = s_n;
            #pragma unroll
            for (int i = 0; i < 8; i++) { warp_off[i] = s; s += warp_cnt[i]; }
            s_n = s;
        }
        __syncthreads();
        if (p) {
            int pos = warp_off[w] + __popc(bal & ((1u << lane) - 1u));
            if (pos < MAXN) s_idx[pos] = n;
        }
        __syncthreads();
    }
    const int Nc = min(s_n, MAXN);

    if (Nc == 0) {
        for (int x = tid; x < KP*DD; x += 256)
            pnew[(size_t)c*KP*DD + x] = proto[(size_t)c*KP*DD + x];
        return;
    }

    for (int i = tid; i < Nc; i += 256) {
        const float* lp = logits + (size_t)s_idx[i]*JJ + c*KP;
        #pragma unroll
        for (int k = 0; k < KP; k++) Q[k][i] = expf(lp[k] * 20.0f);
    }
    __syncthreads();

    float s = 0.0f;
    for (int k = 0; k < KP; k++)
        for (int i = tid; i < Nc; i += 256) s += Q[k][i];
    red[tid] = s; __syncthreads();
    for (int o = 128; o > 0; o >>= 1) { if (tid < o) red[tid] += red[tid+o]; __syncthreads(); }
    float tot = red[0];
    __syncthreads();
    float dTot = (tot > 0.0f) ? tot : 1.0f;
    for (int k = 0; k < KP; k++)
        for (int i = tid; i < Nc; i += 256) Q[k][i] /= dTot;
    __syncthreads();

    const float fNc = (float)Nc;
    for (int it = 0; it < 3; it++) {
        for (int k = 0; k < KP; k++) {
            float rs = 0.0f;
            for (int i = tid; i < Nc; i += 256) rs += Q[k][i];
            red[tid] = rs; __syncthreads();
            for (int o = 128; o > 0; o >>= 1) { if (tid < o) red[tid] += red[tid+o]; __syncthreads(); }
            float r = red[0];
            __syncthreads();
            float dr = (r > 0.0f) ? r : 1.0f;
            for (int i = tid; i < Nc; i += 256) Q[k][i] = Q[k][i] / dr / 5.0f;
            __syncthreads();
        }
        for (int i = tid; i < Nc; i += 256) {
            float cs = Q[0][i]+Q[1][i]+Q[2][i]+Q[3][i]+Q[4][i];
            float dc = (cs > 0.0f) ? cs : 1.0f;
            #pragma unroll
            for (int k = 0; k < KP; k++) Q[k][i] = Q[k][i] / dc / fNc;
        }
        __syncthreads();
    }
    for (int k = 0; k < KP; k++)
        for (int i = tid; i < Nc; i += 256) Q[k][i] *= fNc;
    __syncthreads();

    for (int i = tid; i < Nc; i += 256) {
        float best = Q[0][i]; int ba = 0;
        #pragma unroll
        for (int k = 1; k < KP; k++) if (Q[k][i] > best) { best = Q[k][i]; ba = k; }
        assign[s_idx[i]] = (float)(c*KP + ba);
    }
    __syncthreads();

    for (int i = tid; i < Nc; i += 256) {
        float inv = g_inv[s_idx[i]];
        #pragma unroll
        for (int k = 0; k < KP; k++) Q[k][i] *= inv;
    }
    __syncthreads();

    const int d0 = tid * 3;
    float acc[KP][3];
    #pragma unroll
    for (int k = 0; k < KP; k++) { acc[k][0]=0.f; acc[k][1]=0.f; acc[k][2]=0.f; }
    for (int i = 0; i < Nc; i++) {
        const float* xp = rpt + (size_t)s_idx[i]*DD + d0;
        float x0 = xp[0], x1 = xp[1], x2 = xp[2];
        #pragma unroll
        for (int k = 0; k < KP; k++) {
            float q = Q[k][i];
            acc[k][0] = fmaf(q, x0, acc[k][0]);
            acc[k][1] = fmaf(q, x1, acc[k][1]);
            acc[k][2] = fmaf(q, x2, acc[k][2]);
        }
    }
    const float g = 0.999f, og = 1.0f - 0.999f;
    #pragma unroll
    for (int k = 0; k < KP; k++) {
        size_t basep = ((size_t)c*KP + k)*DD + d0;
        #pragma unroll
        for (int j = 0; j < 3; j++)
            pnew[basep + j] = g * proto[basep + j] + og * acc[k][j];
    }
}

// ---------------------------------------------------------------------------
extern "C" void kernel_launch(void* const* d_in, const int* in_sizes, int n_in,
                              void* d_out, int out_size) {
    const float* pt    = (const float*)d_in[0];
    const float* rpt   = (const float*)d_in[1];
    const float* proto = (const float*)d_in[2];
    const float* sa    = (const float*)d_in[3];
    const int*   lbl   = (const int*)  d_in[4];
    float* out = (float*)d_out;

    cudaFuncSetAttribute(gemm_mma_kernel,
                         cudaFuncAttributeMaxDynamicSharedMemorySize, SMEM_GEMM);

    norm_kernel<<<(2*NN + JPAD + 7)/8, 256>>>(pt, rpt, proto);
    sw_kernel<<<1, 256>>>(sa);
    gemm_mma_kernel<<<148, 512, SMEM_GEMM>>>(out + OFF_LOGITS);
    imgmax_kernel<<<(BB*JJ + 255)/256, 256>>>(out + OFF_LOGITS, out + OFF_IMG);
    cls_kernel<<<(BB*NCLS + 255)/256, 256>>>(out + OFF_IMG, out + OFF_CLS);
    sinkhorn_kernel<<<CC, 256>>>(out + OFF_LOGITS, lbl, proto, rpt,
                                 out + OFF_ASGN, out + OFF_PNEW);
}

// round 10
// speedup vs baseline: 1.0077x; 1.0077x over previous
#include <cuda_runtime.h>
#include <cuda_fp16.h>
#include <cstdint>
#include <math.h>

// Problem constants
#define BB 64
#define PP 196
#define DD 768
#define CC 201
#define KP 5
#define NCLS 200
#define NN (BB*PP)        // 12544
#define JJ (CC*KP)        // 1005
#define JPAD 1024

// Output layout
#define OFF_LOGITS 0
#define SZ_LOGITS  (NN*JJ)
#define OFF_IMG    (OFF_LOGITS + SZ_LOGITS)
#define SZ_IMG     (BB*JJ)
#define OFF_CLS    (OFF_IMG + SZ_IMG)
#define SZ_CLS     (BB*NCLS)
#define OFF_ASGN   (OFF_CLS + SZ_CLS)
#define SZ_ASGN    (NN)
#define OFF_PNEW   (OFF_ASGN + SZ_ASGN)
#define SZ_PNEW    (CC*KP*DD)

// Device scratch
__device__ __align__(16) __half g_pth[NN*DD];     // fp16(A)
__device__ __align__(16) __half g_pt2[NN*DD];     // fp16(Ah + 64*(A-Ah))
__device__ __align__(16) __half g_pnh[JPAD*DD];   // fp16(B)
__device__ __align__(16) __half g_pn2[JPAD*DD];   // fp16(Bh + 64*(B-Bh))
__device__ float g_inv[NN];                       // 1/||rpt_row||
__device__ float g_sw[NCLS*KP];

// ---------------------------------------------------------------------------
// PTX helpers
// ---------------------------------------------------------------------------
__device__ __forceinline__ void ldsm_x4(uint32_t* r, uint32_t addr) {
    asm volatile("ldmatrix.sync.aligned.m8n8.x4.shared.b16 {%0,%1,%2,%3}, [%4];"
                 : "=r"(r[0]), "=r"(r[1]), "=r"(r[2]), "=r"(r[3]) : "r"(addr));
}
__device__ __forceinline__ void mma_fp16(float* d, const uint32_t* a, const uint32_t* b) {
    asm volatile(
        "mma.sync.aligned.m16n8k16.row.col.f32.f16.f16.f32 "
        "{%0,%1,%2,%3}, {%4,%5,%6,%7}, {%8,%9}, {%0,%1,%2,%3};"
        : "+f"(d[0]), "+f"(d[1]), "+f"(d[2]), "+f"(d[3])
        : "r"(a[0]), "r"(a[1]), "r"(a[2]), "r"(a[3]), "r"(b[0]), "r"(b[1]));
}
__device__ __forceinline__ void cpa16(uint32_t smem, const void* g) {
    asm volatile("cp.async.ca.shared.global [%0], [%1], 16;" :: "r"(smem), "l"(g));
}
__device__ __forceinline__ void cpa_commit() {
    asm volatile("cp.async.commit_group;" ::: "memory");
}
template <int N>
__device__ __forceinline__ void cpa_wait() {
    asm volatile("cp.async.wait_group %0;" :: "n"(N) : "memory");
}

// ---------------------------------------------------------------------------
// Row L2 normalization + fp16 Ootomo split (warp per row)
// ---------------------------------------------------------------------------
__global__ __launch_bounds__(256) void norm_kernel(const float* __restrict__ pt,
                            const float* __restrict__ rpt,
                            const float* __restrict__ proto) {
    const int r = blockIdx.x * 8 + (threadIdx.x >> 5);
    const int lane = threadIdx.x & 31;
    if (r >= 2*NN + JPAD) return;

    if (r < NN) {
        const float* src = pt + (size_t)r*DD;
        float s = 0.0f;
        for (int i = lane; i < DD; i += 32) { float v = src[i]; s += v*v; }
        #pragma unroll
        for (int o = 16; o > 0; o >>= 1) s += __shfl_xor_sync(0xffffffffu, s, o);
        float inv = 1.0f / fmaxf(sqrtf(s), 1e-12f);
        for (int i = lane; i < DD; i += 32) {
            float x = src[i] * inv;
            __half h = __float2half(x);
            float hf = __half2float(h);
            g_pth[(size_t)r*DD + i] = h;
            g_pt2[(size_t)r*DD + i] = __float2half(fmaf(64.0f, x - hf, hf));
        }
    } else if (r < 2*NN) {
        int rr = r - NN;
        const float* src = rpt + (size_t)rr*DD;
        float s = 0.0f;
        for (int i = lane; i < DD; i += 32) { float v = src[i]; s += v*v; }
        #pragma unroll
        for (int o = 16; o > 0; o >>= 1) s += __shfl_xor_sync(0xffffffffu, s, o);
        if (lane == 0) g_inv[rr] = 1.0f / fmaxf(sqrtf(s), 1e-12f);
    } else {
        int j = r - 2*NN;
        if (j >= JJ) {
            __half z = __float2half(0.0f);
            for (int i = lane; i < DD; i += 32) {
                g_pnh[(size_t)j*DD + i] = z;
                g_pn2[(size_t)j*DD + i] = z;
            }
            return;
        }
        const float* src = proto + (size_t)j*DD;
        float s = 0.0f;
        for (int i = lane; i < DD; i += 32) { float v = src[i]; s += v*v; }
        #pragma unroll
        for (int o = 16; o > 0; o >>= 1) s += __shfl_xor_sync(0xffffffffu, s, o);
        float inv = 1.0f / fmaxf(sqrtf(s), 1e-12f);
        for (int i = lane; i < DD; i += 32) {
            float x = src[i] * inv;
            __half h = __float2half(x);
            float hf = __half2float(h);
            g_pnh[(size_t)j*DD + i] = h;
            g_pn2[(size_t)j*DD + i] = __float2half(fmaf(64.0f, x - hf, hf));
        }
    }
}

// ---------------------------------------------------------------------------
// sw = softmax(sa_weights, axis=-1) * K
// ---------------------------------------------------------------------------
__global__ void sw_kernel(const float* __restrict__ sa) {
    int c = blockIdx.x * blockDim.x + threadIdx.x;
    if (c >= NCLS) return;
    float w[KP];
    float m = -1e30f;
    for (int k = 0; k < KP; k++) { w[k] = sa[c*KP+k]; m = fmaxf(m, w[k]); }
    float s = 0.0f;
    for (int k = 0; k < KP; k++) { w[k] = expf(w[k]-m); s += w[k]; }
    for (int k = 0; k < KP; k++) g_sw[c*KP+k] = w[k] / s * 5.0f;
}

// ---------------------------------------------------------------------------
// 2-product fp16 GEMM (Ootomo):  out = P0 + (P1-P0)/64
// Persistent 148 CTAs x 512 thr; CTA tile 128x128, warp tile 32x32 (4x4 grid),
// both products per warp (register-local epilogue).
// BK=64, 3-stage cp.async ring, one __syncthreads per chunk, loads pipelined
// across tile boundaries (flattened chunk stream).
// ---------------------------------------------------------------------------
#define SAS2 72                              // smem row stride (fp16): 64 + 8 pad
#define ROW_B 144
#define ARR_B (128*ROW_B)                    // 18432 per array
#define STAGE2 (4*ARR_B)                     // 73728 per stage
#define NSTAGE 3
#define SMEM_GEMM (NSTAGE*STAGE2)            // 221184
#define CPT 12                               // chunks per tile (768/64)
#define MTILES (NN/128)                      // 98
#define NTILES (JPAD/128)                    // 8
#define TOTTILES (MTILES*NTILES)             // 784

__global__ __launch_bounds__(512, 1) void gemm_mma_kernel(float* __restrict__ out) {
    extern __shared__ __align__(16) char smem[];
    const uint32_t sb = (uint32_t)__cvta_generic_to_shared(smem);

    const int tid  = threadIdx.x;
    const int lane = tid & 31;
    const int wid  = tid >> 5;
    const int wm   = wid & 3;      // M 32-block
    const int wn   = wid >> 2;     // N 32-block

    const int arow = (lane & 7) + ((lane >> 3) & 1) * 8;
    const int acol = (lane >> 4) * 8;
    const int brow = (lane & 7) + ((lane >> 4) & 1) * 8;
    const int bcol = ((lane >> 3) & 1) * 8;

    const int myTiles = (TOTTILES - blockIdx.x + 147) / 148;
    const int total = myTiles * CPT;

    float acc0[2][4][4], acc1[2][4][4];
    #pragma unroll
    for (int i = 0; i < 2; i++)
        #pragma unroll
        for (int j = 0; j < 4; j++)
            #pragma unroll
            for (int q = 0; q < 4; q++) { acc0[i][j][q] = 0.0f; acc1[i][j][q] = 0.0f; }

    // issue one chunk's loads (64KB): 4096 16B granules, 8 per thread
    auto load_chunk = [&](int c) {
        if (c >= total) return;
        int tile = blockIdx.x + (c / CPT) * 148;
        int bm = (tile / NTILES) * 128;
        int bn = (tile % NTILES) * 128;
        int kt = (c % CPT) * 64;
        uint32_t st = sb + (c % NSTAGE) * STAGE2;
        #pragma unroll
        for (int i = 0; i < 8; i++) {
            int x = i*512 + tid;
            int arr = x >> 10;
            int rem = x & 1023;
            int row = rem >> 3;
            int q = rem & 7;
            uint32_t so = st + arr*ARR_B + row*ROW_B + q*16;
            const __half* src;
            if (arr == 0)      src = g_pth + (size_t)(bm + row)*DD;
            else if (arr == 1) src = g_pt2 + (size_t)(bm + row)*DD;
            else if (arr == 2) src = g_pnh + (size_t)(bn + row)*DD;
            else               src = g_pn2 + (size_t)(bn + row)*DD;
            cpa16(so, src + kt + q*8);
        }
        cpa_commit();
    };

    load_chunk(0);
    load_chunk(1);

    for (int c = 0; c < total; c++) {
        if (c + 2 < total) cpa_wait<1>(); else cpa_wait<0>();
        __syncthreads();
        load_chunk(c + 2);

        const uint32_t base = sb + (c % NSTAGE) * STAGE2;
        const uint32_t aAh = base;
        const uint32_t aA2 = base + ARR_B;
        const uint32_t aBh = base + 2*ARR_B;
        const uint32_t aB2 = base + 3*ARR_B;

        #pragma unroll
        for (int ks = 0; ks < 64; ks += 16) {
            uint32_t ah[2][4], a2[2][4];
            #pragma unroll
            for (int mi = 0; mi < 2; mi++) {
                uint32_t off = (uint32_t)((wm*32 + mi*16 + arow)*SAS2 + ks + acol) * 2;
                ldsm_x4(ah[mi], aAh + off);
                ldsm_x4(a2[mi], aA2 + off);
            }
            #pragma unroll
            for (int nb = 0; nb < 2; nb++) {
                uint32_t bh[4], b2[4];
                uint32_t off = (uint32_t)((wn*32 + nb*16 + brow)*SAS2 + ks + bcol) * 2;
                ldsm_x4(bh, aBh + off);
                ldsm_x4(b2, aB2 + off);
                #pragma unroll
                for (int mi = 0; mi < 2; mi++) {
                    mma_fp16(acc0[mi][nb*2+0], ah[mi], bh+0);
                    mma_fp16(acc0[mi][nb*2+1], ah[mi], bh+2);
                    mma_fp16(acc1[mi][nb*2+0], a2[mi], b2+0);
                    mma_fp16(acc1[mi][nb*2+1], a2[mi], b2+2);
                }
            }
        }

        if ((c % CPT) == CPT - 1) {
            // register-local epilogue for tile c/CPT
            int tile = blockIdx.x + (c / CPT) * 148;
            int bm = (tile / NTILES) * 128;
            int bn = (tile % NTILES) * 128;
            #pragma unroll
            for (int mi = 0; mi < 2; mi++)
                #pragma unroll
                for (int nf = 0; nf < 4; nf++)
                    #pragma unroll
                    for (int q = 0; q < 4; q++) {
                        int rloc = wm*32 + mi*16 + (lane >> 2) + (q >> 1)*8;
                        int cloc = wn*32 + nf*8 + (lane & 3)*2 + (q & 1);
                        int col = bn + cloc;
                        if (col < JJ) {
                            float p0 = acc0[mi][nf][q];
                            float p1 = acc1[mi][nf][q];
                            out[(size_t)(bm + rloc)*JJ + col] =
                                p0 + (p1 - p0) * 0.015625f;
                        }
                        acc0[mi][nf][q] = 0.0f;
                        acc1[mi][nf][q] = 0.0f;
                    }
        }
    }
}

// ---------------------------------------------------------------------------
// image_logits[b, j] = max_p logits[b, p, j]
// ---------------------------------------------------------------------------
__global__ void imgmax_kernel(const float* __restrict__ logits, float* __restrict__ img) {
    int t = blockIdx.x * blockDim.x + threadIdx.x;
    if (t >= BB*JJ) return;
    int b = t / JJ, j = t % JJ;
    const float* p = logits + (size_t)b*PP*JJ + j;
    float m = -1e30f;
    for (int i = 0; i < PP; i++) m = fmaxf(m, p[(size_t)i*JJ]);
    img[(size_t)b*JJ + j] = m;
}

// ---------------------------------------------------------------------------
// class_logits[b, c] = sum_k img[b, c, k]*sw[c, k] / TEMP
// ---------------------------------------------------------------------------
__global__ void cls_kernel(const float* __restrict__ img, float* __restrict__ cls) {
    int t = blockIdx.x * blockDim.x + threadIdx.x;
    if (t >= BB*NCLS) return;
    int b = t / NCLS, c = t % NCLS;
    float s = 0.0f;
    #pragma unroll
    for (int k = 0; k < KP; k++) s += img[(size_t)b*JJ + c*KP + k] * g_sw[c*KP+k];
    cls[t] = s / 0.2f;
}

// ---------------------------------------------------------------------------
// Per-class: deterministic compaction + Sinkhorn + assignment + P_new
// ---------------------------------------------------------------------------
#define MAXN 1024
__global__ __launch_bounds__(256) void sinkhorn_kernel(
        const float* __restrict__ logits, const int* __restrict__ labels,
        const float* __restrict__ proto, const float* __restrict__ rpt,
        float* __restrict__ assign, float* __restrict__ pnew) {
    const int c = blockIdx.x;
    const int tid = threadIdx.x;
    const int lane = tid & 31, w = tid >> 5;

    __shared__ int   s_idx[MAXN];
    __shared__ float Q[KP][MAXN];
    __shared__ float red[256];
    __shared__ int   warp_cnt[8], warp_off[8];
    __shared__ int   s_n;

    if (tid == 0) s_n = 0;
    __syncthreads();

    for (int base = 0; base < NN; base += 256) {
        int n = base + tid;
        bool p = (labels[n] == c);
        unsigned bal = __ballot_sync(0xffffffffu, p);
        if (lane == 0) warp_cnt[w] = __popc(bal);
        __syncthreads();
        if (tid == 0) {
            int s = s_n;
            #pragma unroll
            for (int i = 0; i < 8; i++) { warp_off[i] = s; s += warp_cnt[i]; }
            s_n = s;
        }
        __syncthreads();
        if (p) {
            int pos = warp_off[w] + __popc(bal & ((1u << lane) - 1u));
            if (pos < MAXN) s_idx[pos] = n;
        }
        __syncthreads();
    }
    const int Nc = min(s_n, MAXN);

    if (Nc == 0) {
        for (int x = tid; x < KP*DD; x += 256)
            pnew[(size_t)c*KP*DD + x] = proto[(size_t)c*KP*DD + x];
        return;
    }

    for (int i = tid; i < Nc; i += 256) {
        const float* lp = logits + (size_t)s_idx[i]*JJ + c*KP;
        #pragma unroll
        for (int k = 0; k < KP; k++) Q[k][i] = expf(lp[k] * 20.0f);
    }
    __syncthreads();

    float s = 0.0f;
    for (int k = 0; k < KP; k++)
        for (int i = tid; i < Nc; i += 256) s += Q[k][i];
    red[tid] = s; __syncthreads();
    for (int o = 128; o > 0; o >>= 1) { if (tid < o) red[tid] += red[tid+o]; __syncthreads(); }
    float tot = red[0];
    __syncthreads();
    float dTot = (tot > 0.0f) ? tot : 1.0f;
    for (int k = 0; k < KP; k++)
        for (int i = tid; i < Nc; i += 256) Q[k][i] /= dTot;
    __syncthreads();

    const float fNc = (float)Nc;
    for (int it = 0; it < 3; it++) {
        for (int k = 0; k < KP; k++) {
            float rs = 0.0f;
            for (int i = tid; i < Nc; i += 256) rs += Q[k][i];
            red[tid] = rs; __syncthreads();
            for (int o = 128; o > 0; o >>= 1) { if (tid < o) red[tid] += red[tid+o]; __syncthreads(); }
            float r = red[0];
            __syncthreads();
            float dr = (r > 0.0f) ? r : 1.0f;
            for (int i = tid; i < Nc; i += 256) Q[k][i] = Q[k][i] / dr / 5.0f;
            __syncthreads();
        }
        for (int i = tid; i < Nc; i += 256) {
            float cs = Q[0][i]+Q[1][i]+Q[2][i]+Q[3][i]+Q[4][i];
            float dc = (cs > 0.0f) ? cs : 1.0f;
            #pragma unroll
            for (int k = 0; k < KP; k++) Q[k][i] = Q[k][i] / dc / fNc;
        }
        __syncthreads();
    }
    for (int k = 0; k < KP; k++)
        for (int i = tid; i < Nc; i += 256) Q[k][i] *= fNc;
    __syncthreads();

    for (int i = tid; i < Nc; i += 256) {
        float best = Q[0][i]; int ba = 0;
        #pragma unroll
        for (int k = 1; k < KP; k++) if (Q[k][i] > best) { best = Q[k][i]; ba = k; }
        assign[s_idx[i]] = (float)(c*KP + ba);
    }
    __syncthreads();

    for (int i = tid; i < Nc; i += 256) {
        float inv = g_inv[s_idx[i]];
        #pragma unroll
        for (int k = 0; k < KP; k++) Q[k][i] *= inv;
    }
    __syncthreads();

    const int d0 = tid * 3;
    float acc[KP][3];
    #pragma unroll
    for (int k = 0; k < KP; k++) { acc[k][0]=0.f; acc[k][1]=0.f; acc[k][2]=0.f; }
    for (int i = 0; i < Nc; i++) {
        const float* xp = rpt + (size_t)s_idx[i]*DD + d0;
        float x0 = xp[0], x1 = xp[1], x2 = xp[2];
        #pragma unroll
        for (int k = 0; k < KP; k++) {
            float q = Q[k][i];
            acc[k][0] = fmaf(q, x0, acc[k][0]);
            acc[k][1] = fmaf(q, x1, acc[k][1]);
            acc[k][2] = fmaf(q, x2, acc[k][2]);
        }
    }
    const float g = 0.999f, og = 1.0f - 0.999f;
    #pragma unroll
    for (int k = 0; k < KP; k++) {
        size_t basep = ((size_t)c*KP + k)*DD + d0;
        #pragma unroll
        for (int j = 0; j < 3; j++)
            pnew[basep + j] = g * proto[basep + j] + og * acc[k][j];
    }
}

// ---------------------------------------------------------------------------
extern "C" void kernel_launch(void* const* d_in, const int* in_sizes, int n_in,
                              void* d_out, int out_size) {
    const float* pt    = (const float*)d_in[0];
    const float* rpt   = (const float*)d_in[1];
    const float* proto = (const float*)d_in[2];
    const float* sa    = (const float*)d_in[3];
    const int*   lbl   = (const int*)  d_in[4];
    float* out = (float*)d_out;

    cudaFuncSetAttribute(gemm_mma_kernel,
                         cudaFuncAttributeMaxDynamicSharedMemorySize, SMEM_GEMM);

    norm_kernel<<<(2*NN + JPAD + 7)/8, 256>>>(pt, rpt, proto);
    sw_kernel<<<1, 256>>>(sa);
    gemm_mma_kernel<<<148, 512, SMEM_GEMM>>>(out + OFF_LOGITS);
    imgmax_kernel<<<(BB*JJ + 255)/256, 256>>>(out + OFF_LOGITS, out + OFF_IMG);
    cls_kernel<<<(BB*NCLS + 255)/256, 256>>>(out + OFF_IMG, out + OFF_CLS);
    sinkhorn_kernel<<<CC, 256>>>(out + OFF_LOGITS, lbl, proto, rpt,
                                 out + OFF_ASGN, out + OFF_PNEW);
}

// round 11
// speedup vs baseline: 1.1107x; 1.1022x over previous
#include <cuda_runtime.h>
#include <cuda_fp16.h>
#include <cstdint>
#include <math.h>

// Problem constants
#define BB 64
#define PP 196
#define DD 768
#define CC 201
#define KP 5
#define NCLS 200
#define NN (BB*PP)        // 12544
#define JJ (CC*KP)        // 1005
#define JPAD 1024

// Output layout
#define OFF_LOGITS 0
#define SZ_LOGITS  (NN*JJ)
#define OFF_IMG    (OFF_LOGITS + SZ_LOGITS)
#define SZ_IMG     (BB*JJ)
#define OFF_CLS    (OFF_IMG + SZ_IMG)
#define SZ_CLS     (BB*NCLS)
#define OFF_ASGN   (OFF_CLS + SZ_CLS)
#define SZ_ASGN    (NN)
#define OFF_PNEW   (OFF_ASGN + SZ_ASGN)
#define SZ_PNEW    (CC*KP*DD)

// Device scratch
__device__ __align__(16) __half g_pth[NN*DD];     // fp16(A)
__device__ __align__(16) __half g_pt2[NN*DD];     // fp16(Ah + 64*(A-Ah))
__device__ __align__(16) __half g_pnh[JPAD*DD];   // fp16(B)
__device__ __align__(16) __half g_pn2[JPAD*DD];   // fp16(Bh + 64*(B-Bh))
__device__ float g_inv[NN];                       // 1/||rpt_row||
__device__ float g_sw[NCLS*KP];

// ---------------------------------------------------------------------------
// PTX helpers
// ---------------------------------------------------------------------------
__device__ __forceinline__ void ldsm_x4(uint32_t* r, uint32_t addr) {
    asm volatile("ldmatrix.sync.aligned.m8n8.x4.shared.b16 {%0,%1,%2,%3}, [%4];"
                 : "=r"(r[0]), "=r"(r[1]), "=r"(r[2]), "=r"(r[3]) : "r"(addr));
}
__device__ __forceinline__ void mma_fp16(float* d, const uint32_t* a, const uint32_t* b) {
    asm volatile(
        "mma.sync.aligned.m16n8k16.row.col.f32.f16.f16.f32 "
        "{%0,%1,%2,%3}, {%4,%5,%6,%7}, {%8,%9}, {%0,%1,%2,%3};"
        : "+f"(d[0]), "+f"(d[1]), "+f"(d[2]), "+f"(d[3])
        : "r"(a[0]), "r"(a[1]), "r"(a[2]), "r"(a[3]), "r"(b[0]), "r"(b[1]));
}
__device__ __forceinline__ void cpa16(uint32_t smem, const void* g) {
    asm volatile("cp.async.ca.shared.global [%0], [%1], 16;" :: "r"(smem), "l"(g));
}
__device__ __forceinline__ void cpa_commit() {
    asm volatile("cp.async.commit_group;" ::: "memory");
}
template <int N>
__device__ __forceinline__ void cpa_wait() {
    asm volatile("cp.async.wait_group %0;" :: "n"(N) : "memory");
}

// ---------------------------------------------------------------------------
// padding no-op kernel (shifts ncu capture window onto the GEMM launch)
// ---------------------------------------------------------------------------
__global__ void pad_kernel() {}

// ---------------------------------------------------------------------------
// Row L2 normalization + fp16 Ootomo split (warp per row)
// ---------------------------------------------------------------------------
__global__ __launch_bounds__(256) void norm_kernel(const float* __restrict__ pt,
                            const float* __restrict__ rpt,
                            const float* __restrict__ proto) {
    const int r = blockIdx.x * 8 + (threadIdx.x >> 5);
    const int lane = threadIdx.x & 31;
    if (r >= 2*NN + JPAD) return;

    if (r < NN) {
        const float* src = pt + (size_t)r*DD;
        float s = 0.0f;
        for (int i = lane; i < DD; i += 32) { float v = src[i]; s += v*v; }
        #pragma unroll
        for (int o = 16; o > 0; o >>= 1) s += __shfl_xor_sync(0xffffffffu, s, o);
        float inv = 1.0f / fmaxf(sqrtf(s), 1e-12f);
        for (int i = lane; i < DD; i += 32) {
            float x = src[i] * inv;
            __half h = __float2half(x);
            float hf = __half2float(h);
            g_pth[(size_t)r*DD + i] = h;
            g_pt2[(size_t)r*DD + i] = __float2half(fmaf(64.0f, x - hf, hf));
        }
    } else if (r < 2*NN) {
        int rr = r - NN;
        const float* src = rpt + (size_t)rr*DD;
        float s = 0.0f;
        for (int i = lane; i < DD; i += 32) { float v = src[i]; s += v*v; }
        #pragma unroll
        for (int o = 16; o > 0; o >>= 1) s += __shfl_xor_sync(0xffffffffu, s, o);
        if (lane == 0) g_inv[rr] = 1.0f / fmaxf(sqrtf(s), 1e-12f);
    } else {
        int j = r - 2*NN;
        if (j >= JJ) {
            __half z = __float2half(0.0f);
            for (int i = lane; i < DD; i += 32) {
                g_pnh[(size_t)j*DD + i] = z;
                g_pn2[(size_t)j*DD + i] = z;
            }
            return;
        }
        const float* src = proto + (size_t)j*DD;
        float s = 0.0f;
        for (int i = lane; i < DD; i += 32) { float v = src[i]; s += v*v; }
        #pragma unroll
        for (int o = 16; o > 0; o >>= 1) s += __shfl_xor_sync(0xffffffffu, s, o);
        float inv = 1.0f / fmaxf(sqrtf(s), 1e-12f);
        for (int i = lane; i < DD; i += 32) {
            float x = src[i] * inv;
            __half h = __float2half(x);
            float hf = __half2float(h);
            g_pnh[(size_t)j*DD + i] = h;
            g_pn2[(size_t)j*DD + i] = __float2half(fmaf(64.0f, x - hf, hf));
        }
    }
}

// ---------------------------------------------------------------------------
// sw = softmax(sa_weights, axis=-1) * K
// ---------------------------------------------------------------------------
__global__ void sw_kernel(const float* __restrict__ sa) {
    int c = blockIdx.x * blockDim.x + threadIdx.x;
    if (c >= NCLS) return;
    float w[KP];
    float m = -1e30f;
    for (int k = 0; k < KP; k++) { w[k] = sa[c*KP+k]; m = fmaxf(m, w[k]); }
    float s = 0.0f;
    for (int k = 0; k < KP; k++) { w[k] = expf(w[k]-m); s += w[k]; }
    for (int k = 0; k < KP; k++) g_sw[c*KP+k] = w[k] / s * 5.0f;
}

// ---------------------------------------------------------------------------
// 2-product fp16 GEMM (Ootomo):  out = P0 + (P1 - P0)/64
// CTA 128x64, BK=64, 8 warps (4M x 2N), warp tile 32x32, 2-stage cp.async,
// 2 CTAs/SM.  (R6 config with BK doubled: 12 chunks instead of 24.)
// ---------------------------------------------------------------------------
#define SAS2 72                              // smem row stride (fp16): 64 + 8 pad
#define ROW_B 144                            // bytes per row
#define A_TB (128*ROW_B)                     // 18432 per A array
#define B_TB (64*ROW_B)                      // 9216 per B array
#define STAGE_B (2*A_TB + 2*B_TB)            // 55296 per stage
#define SMEM_GEMM (2*STAGE_B)                // 110592
#define NCHUNK (DD/64)                       // 12

__global__ __launch_bounds__(256, 2) void gemm_mma_kernel(float* __restrict__ out) {
    extern __shared__ __align__(16) char smem[];
    const uint32_t sb = (uint32_t)__cvta_generic_to_shared(smem);

    const int tid  = threadIdx.x;
    const int lane = tid & 31;
    const int wid  = tid >> 5;
    const int wm   = wid & 3;      // M 32-block
    const int wn   = wid >> 2;     // N 32-block
    const int bm   = blockIdx.x * 128;
    const int bn   = blockIdx.y * 64;

    const int arow = (lane & 7) + ((lane >> 3) & 1) * 8;
    const int acol = (lane >> 4) * 8;
    const int brow = (lane & 7) + ((lane >> 4) & 1) * 8;
    const int bcol = ((lane >> 3) & 1) * 8;

    float acc0[2][4][4], acc1[2][4][4];
    #pragma unroll
    for (int i = 0; i < 2; i++)
        #pragma unroll
        for (int j = 0; j < 4; j++)
            #pragma unroll
            for (int q = 0; q < 4; q++) { acc0[i][j][q] = 0.0f; acc1[i][j][q] = 0.0f; }

    // loader: 3072 16B granules per chunk (Ah 1024, A2 1024, Bh 512, B2 512)
    auto load_chunk = [&](int kt, int s) {
        uint32_t st = sb + s*STAGE_B;
        #pragma unroll
        for (int i = 0; i < 12; i++) {
            int x = i*256 + tid;
            uint32_t dst;
            const __half* src;
            if (x < 2048) {
                int arr = x >> 10;             // 0 = Ah, 1 = A2
                int rem = x & 1023;
                int row = rem >> 3, q = rem & 7;
                dst = st + arr*A_TB + (uint32_t)(row*ROW_B + q*16);
                src = (arr ? g_pt2 : g_pth) + (size_t)(bm + row)*DD + kt + q*8;
            } else {
                int arr = (x - 2048) >> 9;     // 0 = Bh, 1 = B2
                int rem = x & 511;
                int row = rem >> 3, q = rem & 7;
                dst = st + 2*A_TB + arr*B_TB + (uint32_t)(row*ROW_B + q*16);
                src = (arr ? g_pn2 : g_pnh) + (size_t)(bn + row)*DD + kt + q*8;
            }
            cpa16(dst, src);
        }
        cpa_commit();
    };

    load_chunk(0, 0);

    for (int i = 0; i < NCHUNK; i++) {
        const int s = i & 1;
        if (i + 1 < NCHUNK) {
            load_chunk((i+1)*64, (i+1) & 1);
            cpa_wait<1>();
        } else {
            cpa_wait<0>();
        }
        __syncthreads();

        const uint32_t aAh = sb + s*STAGE_B;
        const uint32_t aA2 = aAh + A_TB;
        const uint32_t aBh = aAh + 2*A_TB;
        const uint32_t aB2 = aBh + B_TB;

        #pragma unroll
        for (int ks = 0; ks < 64; ks += 16) {
            uint32_t ah[2][4], a2[2][4];
            #pragma unroll
            for (int mi = 0; mi < 2; mi++) {
                uint32_t off = (uint32_t)((wm*32 + mi*16 + arow)*SAS2 + ks + acol) * 2;
                ldsm_x4(ah[mi], aAh + off);
                ldsm_x4(a2[mi], aA2 + off);
            }
            #pragma unroll
            for (int nb = 0; nb < 2; nb++) {
                uint32_t bh[4], b2[4];
                uint32_t off = (uint32_t)((wn*32 + nb*16 + brow)*SAS2 + ks + bcol) * 2;
                ldsm_x4(bh, aBh + off);
                ldsm_x4(b2, aB2 + off);
                #pragma unroll
                for (int mi = 0; mi < 2; mi++) {
                    mma_fp16(acc0[mi][nb*2+0], ah[mi], bh+0);
                    mma_fp16(acc0[mi][nb*2+1], ah[mi], bh+2);
                    mma_fp16(acc1[mi][nb*2+0], a2[mi], b2+0);
                    mma_fp16(acc1[mi][nb*2+1], a2[mi], b2+2);
                }
            }
        }
        __syncthreads();
    }

    // epilogue: combine P0 + (P1-P0)/64, scalar fp32 stores (JJ odd)
    #pragma unroll
    for (int mi = 0; mi < 2; mi++) {
        #pragma unroll
        for (int nf = 0; nf < 4; nf++) {
            int col = bn + wn*32 + nf*8 + (lane & 3)*2;
            #pragma unroll
            for (int h = 0; h < 2; h++) {
                int row = bm + wm*32 + mi*16 + (lane >> 2) + h*8;
                size_t base = (size_t)row*JJ + col;
                float p0a = acc0[mi][nf][h*2+0], p1a = acc1[mi][nf][h*2+0];
                float p0b = acc0[mi][nf][h*2+1], p1b = acc1[mi][nf][h*2+1];
                float va = p0a + (p1a - p0a) * 0.015625f;
                float vb = p0b + (p1b - p0b) * 0.015625f;
                if (col < JJ)     out[base]     = va;
                if (col + 1 < JJ) out[base + 1] = vb;
            }
        }
    }
}

// ---------------------------------------------------------------------------
// image_logits[b, j] = max_p logits[b, p, j]
// ---------------------------------------------------------------------------
__global__ void imgmax_kernel(const float* __restrict__ logits, float* __restrict__ img) {
    int t = blockIdx.x * blockDim.x + threadIdx.x;
    if (t >= BB*JJ) return;
    int b = t / JJ, j = t % JJ;
    const float* p = logits + (size_t)b*PP*JJ + j;
    float m = -1e30f;
    for (int i = 0; i < PP; i++) m = fmaxf(m, p[(size_t)i*JJ]);
    img[(size_t)b*JJ + j] = m;
}

// ---------------------------------------------------------------------------
// class_logits[b, c] = sum_k img[b, c, k]*sw[c, k] / TEMP
// ---------------------------------------------------------------------------
__global__ void cls_kernel(const float* __restrict__ img, float* __restrict__ cls) {
    int t = blockIdx.x * blockDim.x + threadIdx.x;
    if (t >= BB*NCLS) return;
    int b = t / NCLS, c = t % NCLS;
    float s = 0.0f;
    #pragma unroll
    for (int k = 0; k < KP; k++) s += img[(size_t)b*JJ + c*KP + k] * g_sw[c*KP+k];
    cls[t] = s / 0.2f;
}

// ---------------------------------------------------------------------------
// Per-class: deterministic compaction + Sinkhorn + assignment + P_new
// ---------------------------------------------------------------------------
#define MAXN 1024
__global__ __launch_bounds__(256) void sinkhorn_kernel(
        const float* __restrict__ logits, const int* __restrict__ labels,
        const float* __restrict__ proto, const float* __restrict__ rpt,
        float* __restrict__ assign, float* __restrict__ pnew) {
    const int c = blockIdx.x;
    const int tid = threadIdx.x;
    const int lane = tid & 31, w = tid >> 5;

    __shared__ int   s_idx[MAXN];
    __shared__ float Q[KP][MAXN];
    __shared__ float red[256];
    __shared__ int   warp_cnt[8], warp_off[8];
    __shared__ int   s_n;

    if (tid == 0) s_n = 0;
    __syncthreads();

    for (int base = 0; base < NN; base += 256) {
        int n = base + tid;
        bool p = (labels[n] == c);
        unsigned bal = __ballot_sync(0xffffffffu, p);
        if (lane == 0) warp_cnt[w] = __popc(bal);
        __syncthreads();
        if (tid == 0) {
            int s = s_n;
            #pragma unroll
            for (int i = 0; i < 8; i++) { warp_off[i] = s; s += warp_cnt[i]; }
            s_n = s;
        }
        __syncthreads();
        if (p) {
            int pos = warp_off[w] + __popc(bal & ((1u << lane) - 1u));
            if (pos < MAXN) s_idx[pos] = n;
        }
        __syncthreads();
    }
    const int Nc = min(s_n, MAXN);

    if (Nc == 0) {
        for (int x = tid; x < KP*DD; x += 256)
            pnew[(size_t)c*KP*DD + x] = proto[(size_t)c*KP*DD + x];
        return;
    }

    for (int i = tid; i < Nc; i += 256) {
        const float* lp = logits + (size_t)s_idx[i]*JJ + c*KP;
        #pragma unroll
        for (int k = 0; k < KP; k++) Q[k][i] = expf(lp[k] * 20.0f);
    }
    __syncthreads();

    float s = 0.0f;
    for (int k = 0; k < KP; k++)
        for (int i = tid; i < Nc; i += 256) s += Q[k][i];
    red[tid] = s; __syncthreads();
    for (int o = 128; o > 0; o >>= 1) { if (tid < o) red[tid] += red[tid+o]; __syncthreads(); }
    float tot = red[0];
    __syncthreads();
    float dTot = (tot > 0.0f) ? tot : 1.0f;
    for (int k = 0; k < KP; k++)
        for (int i = tid; i < Nc; i += 256) Q[k][i] /= dTot;
    __syncthreads();

    const float fNc = (float)Nc;
    for (int it = 0; it < 3; it++) {
        for (int k = 0; k < KP; k++) {
            float rs = 0.0f;
            for (int i = tid; i < Nc; i += 256) rs += Q[k][i];
            red[tid] = rs; __syncthreads();
            for (int o = 128; o > 0; o >>= 1) { if (tid < o) red[tid] += red[tid+o]; __syncthreads(); }
            float r = red[0];
            __syncthreads();
            float dr = (r > 0.0f) ? r : 1.0f;
            for (int i = tid; i < Nc; i += 256) Q[k][i] = Q[k][i] / dr / 5.0f;
            __syncthreads();
        }
        for (int i = tid; i < Nc; i += 256) {
            float cs = Q[0][i]+Q[1][i]+Q[2][i]+Q[3][i]+Q[4][i];
            float dc = (cs > 0.0f) ? cs : 1.0f;
            #pragma unroll
            for (int k = 0; k < KP; k++) Q[k][i] = Q[k][i] / dc / fNc;
        }
        __syncthreads();
    }
    for (int k = 0; k < KP; k++)
        for (int i = tid; i < Nc; i += 256) Q[k][i] *= fNc;
    __syncthreads();

    for (int i = tid; i < Nc; i += 256) {
        float best = Q[0][i]; int ba = 0;
        #pragma unroll
        for (int k = 1; k < KP; k++) if (Q[k][i] > best) { best = Q[k][i]; ba = k; }
        assign[s_idx[i]] = (float)(c*KP + ba);
    }
    __syncthreads();

    for (int i = tid; i < Nc; i += 256) {
        float inv = g_inv[s_idx[i]];
        #pragma unroll
        for (int k = 0; k < KP; k++) Q[k][i] *= inv;
    }
    __syncthreads();

    const int d0 = tid * 3;
    float acc[KP][3];
    #pragma unroll
    for (int k = 0; k < KP; k++) { acc[k][0]=0.f; acc[k][1]=0.f; acc[k][2]=0.f; }
    for (int i = 0; i < Nc; i++) {
        const float* xp = rpt + (size_t)s_idx[i]*DD + d0;
        float x0 = xp[0], x1 = xp[1], x2 = xp[2];
        #pragma unroll
        for (int k = 0; k < KP; k++) {
            float q = Q[k][i];
            acc[k][0] = fmaf(q, x0, acc[k][0]);
            acc[k][1] = fmaf(q, x1, acc[k][1]);
            acc[k][2] = fmaf(q, x2, acc[k][2]);
        }
    }
    const float g = 0.999f, og = 1.0f - 0.999f;
    #pragma unroll
    for (int k = 0; k < KP; k++) {
        size_t basep = ((size_t)c*KP + k)*DD + d0;
        #pragma unroll
        for (int j = 0; j < 3; j++)
            pnew[basep + j] = g * proto[basep + j] + og * acc[k][j];
    }
}

// ---------------------------------------------------------------------------
extern "C" void kernel_launch(void* const* d_in, const int* in_sizes, int n_in,
                              void* d_out, int out_size) {
    const float* pt    = (const float*)d_in[0];
    const float* rpt   = (const float*)d_in[1];
    const float* proto = (const float*)d_in[2];
    const float* sa    = (const float*)d_in[3];
    const int*   lbl   = (const int*)  d_in[4];
    float* out = (float*)d_out;

    cudaFuncSetAttribute(gemm_mma_kernel,
                         cudaFuncAttributeMaxDynamicSharedMemorySize, SMEM_GEMM);

    pad_kernel<<<1, 32>>>();                              // shifts ncu window onto GEMM
    norm_kernel<<<(2*NN + JPAD + 7)/8, 256>>>(pt, rpt, proto);
    sw_kernel<<<1, 256>>>(sa);
    {
        dim3 grid(NN/128, JPAD/64);   // 98 x 16
        gemm_mma_kernel<<<grid, 256, SMEM_GEMM>>>(out + OFF_LOGITS);
    }
    imgmax_kernel<<<(BB*JJ + 255)/256, 256>>>(out + OFF_LOGITS, out + OFF_IMG);
    cls_kernel<<<(BB*NCLS + 255)/256, 256>>>(out + OFF_IMG, out + OFF_CLS);
    sinkhorn_kernel<<<CC, 256>>>(out + OFF_LOGITS, lbl, proto, rpt,
                                 out + OFF_ASGN, out + OFF_PNEW);
}

// round 12
// speedup vs baseline: 1.1722x; 1.0554x over previous
#include <cuda_runtime.h>
#include <cuda_fp16.h>
#include <cstdint>
#include <math.h>

// Problem constants
#define BB 64
#define PP 196
#define DD 768
#define CC 201
#define KP 5
#define NCLS 200
#define NN (BB*PP)        // 12544
#define JJ (CC*KP)        // 1005
#define JPAD 1024

// Output layout
#define OFF_LOGITS 0
#define SZ_LOGITS  (NN*JJ)
#define OFF_IMG    (OFF_LOGITS + SZ_LOGITS)
#define SZ_IMG     (BB*JJ)
#define OFF_CLS    (OFF_IMG + SZ_IMG)
#define SZ_CLS     (BB*NCLS)
#define OFF_ASGN   (OFF_CLS + SZ_CLS)
#define SZ_ASGN    (NN)
#define OFF_PNEW   (OFF_ASGN + SZ_ASGN)
#define SZ_PNEW    (CC*KP*DD)

// Device scratch
__device__ __align__(16) __half g_pth[NN*DD];     // fp16(A)
__device__ __align__(16) __half g_pt2[NN*DD];     // fp16(Ah + 64*(A-Ah))
__device__ __align__(16) __half g_pnh[JPAD*DD];   // fp16(B)
__device__ __align__(16) __half g_pn2[JPAD*DD];   // fp16(Bh + 64*(B-Bh))
__device__ float g_inv[NN];                       // 1/||rpt_row||
__device__ float g_sw[NCLS*KP];

// ---------------------------------------------------------------------------
// PTX helpers
// ---------------------------------------------------------------------------
__device__ __forceinline__ void ldsm_x4(uint32_t* r, uint32_t addr) {
    asm volatile("ldmatrix.sync.aligned.m8n8.x4.shared.b16 {%0,%1,%2,%3}, [%4];"
                 : "=r"(r[0]), "=r"(r[1]), "=r"(r[2]), "=r"(r[3]) : "r"(addr));
}
__device__ __forceinline__ void mma_fp16(float* d, const uint32_t* a, const uint32_t* b) {
    asm volatile(
        "mma.sync.aligned.m16n8k16.row.col.f32.f16.f16.f32 "
        "{%0,%1,%2,%3}, {%4,%5,%6,%7}, {%8,%9}, {%0,%1,%2,%3};"
        : "+f"(d[0]), "+f"(d[1]), "+f"(d[2]), "+f"(d[3])
        : "r"(a[0]), "r"(a[1]), "r"(a[2]), "r"(a[3]), "r"(b[0]), "r"(b[1]));
}
__device__ __forceinline__ void cpa16(uint32_t smem, const void* g) {
    asm volatile("cp.async.ca.shared.global [%0], [%1], 16;" :: "r"(smem), "l"(g));
}
__device__ __forceinline__ void cpa_commit() {
    asm volatile("cp.async.commit_group;" ::: "memory");
}
template <int N>
__device__ __forceinline__ void cpa_wait() {
    asm volatile("cp.async.wait_group %0;" :: "n"(N) : "memory");
}

// ---------------------------------------------------------------------------
// padding no-op kernel (keeps ncu capture window on the GEMM launch)
// ---------------------------------------------------------------------------
__global__ void pad_kernel() {}

// ---------------------------------------------------------------------------
// Row L2 normalization + fp16 Ootomo split (warp per row, float4 loads)
// ---------------------------------------------------------------------------
__global__ __launch_bounds__(256) void norm_kernel(const float* __restrict__ pt,
                            const float* __restrict__ rpt,
                            const float* __restrict__ proto) {
    const int r = blockIdx.x * 8 + (threadIdx.x >> 5);
    const int lane = threadIdx.x & 31;
    if (r >= 2*NN + JPAD) return;

    if (r < NN) {
        const float4* src = (const float4*)(pt + (size_t)r*DD);   // 192 float4
        float s = 0.0f;
        float4 v[6];
        #pragma unroll
        for (int i = 0; i < 6; i++) {
            v[i] = src[lane + i*32];
            s += v[i].x*v[i].x + v[i].y*v[i].y + v[i].z*v[i].z + v[i].w*v[i].w;
        }
        #pragma unroll
        for (int o = 16; o > 0; o >>= 1) s += __shfl_xor_sync(0xffffffffu, s, o);
        float inv = 1.0f / fmaxf(sqrtf(s), 1e-12f);
        #pragma unroll
        for (int i = 0; i < 6; i++) {
            float x[4] = {v[i].x*inv, v[i].y*inv, v[i].z*inv, v[i].w*inv};
            __half2 h2[2], l2[2];
            #pragma unroll
            for (int j = 0; j < 2; j++) {
                __half h0 = __float2half(x[j*2]),  h1 = __float2half(x[j*2+1]);
                float f0 = __half2float(h0),        f1 = __half2float(h1);
                h2[j] = __halves2half2(h0, h1);
                l2[j] = __halves2half2(__float2half(fmaf(64.0f, x[j*2]-f0, f0)),
                                       __float2half(fmaf(64.0f, x[j*2+1]-f1, f1)));
            }
            size_t o4 = (size_t)r*DD + (lane + i*32)*4;
            *(__half2*)(g_pth + o4)     = h2[0];
            *(__half2*)(g_pth + o4 + 2) = h2[1];
            *(__half2*)(g_pt2 + o4)     = l2[0];
            *(__half2*)(g_pt2 + o4 + 2) = l2[1];
        }
    } else if (r < 2*NN) {
        int rr = r - NN;
        const float4* src = (const float4*)(rpt + (size_t)rr*DD);
        float s = 0.0f;
        #pragma unroll
        for (int i = 0; i < 6; i++) {
            float4 v = src[lane + i*32];
            s += v.x*v.x + v.y*v.y + v.z*v.z + v.w*v.w;
        }
        #pragma unroll
        for (int o = 16; o > 0; o >>= 1) s += __shfl_xor_sync(0xffffffffu, s, o);
        if (lane == 0) g_inv[rr] = 1.0f / fmaxf(sqrtf(s), 1e-12f);
    } else {
        int j = r - 2*NN;
        if (j >= JJ) {
            __half z = __float2half(0.0f);
            for (int i = lane; i < DD; i += 32) {
                g_pnh[(size_t)j*DD + i] = z;
                g_pn2[(size_t)j*DD + i] = z;
            }
            return;
        }
        const float* src = proto + (size_t)j*DD;
        float s = 0.0f;
        for (int i = lane; i < DD; i += 32) { float v = src[i]; s += v*v; }
        #pragma unroll
        for (int o = 16; o > 0; o >>= 1) s += __shfl_xor_sync(0xffffffffu, s, o);
        float inv = 1.0f / fmaxf(sqrtf(s), 1e-12f);
        for (int i = lane; i < DD; i += 32) {
            float x = src[i] * inv;
            __half h = __float2half(x);
            float hf = __half2float(h);
            g_pnh[(size_t)j*DD + i] = h;
            g_pn2[(size_t)j*DD + i] = __float2half(fmaf(64.0f, x - hf, hf));
        }
    }
}

// ---------------------------------------------------------------------------
// sw = softmax(sa_weights, axis=-1) * K
// ---------------------------------------------------------------------------
__global__ void sw_kernel(const float* __restrict__ sa) {
    int c = blockIdx.x * blockDim.x + threadIdx.x;
    if (c >= NCLS) return;
    float w[KP];
    float m = -1e30f;
    for (int k = 0; k < KP; k++) { w[k] = sa[c*KP+k]; m = fmaxf(m, w[k]); }
    float s = 0.0f;
    for (int k = 0; k < KP; k++) { w[k] = expf(w[k]-m); s += w[k]; }
    for (int k = 0; k < KP; k++) g_sw[c*KP+k] = w[k] / s * 5.0f;
}

// ---------------------------------------------------------------------------
// 2-product fp16 GEMM (Ootomo, product-split warps):  out = P0 + (P1-P0)/64
// CTA 128x128, 512 thr = 16 warps: tile (wid&7) = 4Mx2N of 32x64 per product,
// product = wid>>3.  BK=64, 2-stage cp.async, 1 CTA/SM.
// smem traffic per SM-chunk: 196KB read + 64KB write ~= tensor floor (balanced).
// ---------------------------------------------------------------------------
#define SAS2 72                              // smem row stride (fp16): 64 + 8 pad
#define ROW_B 144                            // bytes per row
#define ARR_B (128*ROW_B)                    // 18432 per array (128 rows)
#define STAGE_B (4*ARR_B)                    // Ah, A2, Bh, B2 -> 73728 per stage
#define SMEM_GEMM (2*STAGE_B)                // 147456
#define NCHUNK (DD/64)                       // 12

__global__ __launch_bounds__(512, 1) void gemm_mma_kernel(float* __restrict__ out) {
    extern __shared__ __align__(16) char smem[];
    const uint32_t sb = (uint32_t)__cvta_generic_to_shared(smem);

    const int tid  = threadIdx.x;
    const int lane = tid & 31;
    const int wid  = tid >> 5;
    const int p    = wid >> 3;     // product: 0 -> (Ah,Bh), 1 -> (A2,B2)
    const int t    = wid & 7;      // output tile
    const int wm   = t & 3;        // M 32-block
    const int wn   = t >> 2;       // N 64-block
    const int bm   = blockIdx.x * 128;
    const int bn   = blockIdx.y * 128;

    const int arow = (lane & 7) + ((lane >> 3) & 1) * 8;
    const int acol = (lane >> 4) * 8;
    const int brow = (lane & 7) + ((lane >> 4) & 1) * 8;
    const int bcol = ((lane >> 3) & 1) * 8;

    const uint32_t offA = (uint32_t)p * ARR_B;          // Ah or A2
    const uint32_t offB = (uint32_t)(2 + p) * ARR_B;    // Bh or B2

    float acc[2][8][4];
    #pragma unroll
    for (int i = 0; i < 2; i++)
        #pragma unroll
        for (int j = 0; j < 8; j++)
            #pragma unroll
            for (int q = 0; q < 4; q++) acc[i][j][q] = 0.0f;

    // loader: 4096 16B granules per chunk (4 arrays x 128 rows x 8), 8/thread
    auto load_chunk = [&](int kt, int s) {
        uint32_t st = sb + s*STAGE_B;
        #pragma unroll
        for (int i = 0; i < 8; i++) {
            int x = i*512 + tid;
            int arr = x >> 10;             // 0 Ah, 1 A2, 2 Bh, 3 B2
            int rem = x & 1023;
            int row = rem >> 3, q = rem & 7;
            uint32_t dst = st + arr*ARR_B + (uint32_t)(row*ROW_B + q*16);
            const __half* src;
            if (arr == 0)      src = g_pth + (size_t)(bm + row)*DD;
            else if (arr == 1) src = g_pt2 + (size_t)(bm + row)*DD;
            else if (arr == 2) src = g_pnh + (size_t)(bn + row)*DD;
            else               src = g_pn2 + (size_t)(bn + row)*DD;
            cpa16(dst, src + kt + q*8);
        }
        cpa_commit();
    };

    load_chunk(0, 0);

    for (int i = 0; i < NCHUNK; i++) {
        const int s = i & 1;
        if (i + 1 < NCHUNK) {
            load_chunk((i+1)*64, (i+1) & 1);
            cpa_wait<1>();
        } else {
            cpa_wait<0>();
        }
        __syncthreads();

        const uint32_t aA = sb + s*STAGE_B + offA;
        const uint32_t aB = sb + s*STAGE_B + offB;

        #pragma unroll
        for (int ks = 0; ks < 64; ks += 16) {
            uint32_t af[2][4];
            #pragma unroll
            for (int mi = 0; mi < 2; mi++) {
                uint32_t off = (uint32_t)((wm*32 + mi*16 + arow)*SAS2 + ks + acol) * 2;
                ldsm_x4(af[mi], aA + off);
            }
            #pragma unroll
            for (int nb = 0; nb < 4; nb++) {
                uint32_t bf[4];
                uint32_t off = (uint32_t)((wn*64 + nb*16 + brow)*SAS2 + ks + bcol) * 2;
                ldsm_x4(bf, aB + off);
                #pragma unroll
                for (int mi = 0; mi < 2; mi++) {
                    mma_fp16(acc[mi][nb*2+0], af[mi], bf+0);
                    mma_fp16(acc[mi][nb*2+1], af[mi], bf+2);
                }
            }
        }
        __syncthreads();
    }

    // epilogue: P1 warps stage to smem (aliases stage0, synced); P0 combine+store
    float* xbuf = (float*)smem;     // 8 tiles x 2048 floats = 64KB < SMEM_GEMM
    if (p == 1) {
        float* tb = xbuf + t*2048;
        #pragma unroll
        for (int mi = 0; mi < 2; mi++)
            #pragma unroll
            for (int nf = 0; nf < 8; nf++)
                #pragma unroll
                for (int q = 0; q < 4; q++) {
                    int row = mi*16 + (lane >> 2) + (q >> 1)*8;
                    int col = nf*8 + (lane & 3)*2 + (q & 1);
                    tb[row*64 + col] = acc[mi][nf][q];
                }
    }
    __syncthreads();
    if (p == 0) {
        const float* tb = xbuf + t*2048;
        #pragma unroll
        for (int mi = 0; mi < 2; mi++)
            #pragma unroll
            for (int nf = 0; nf < 8; nf++)
                #pragma unroll
                for (int q = 0; q < 4; q++) {
                    int rloc = mi*16 + (lane >> 2) + (q >> 1)*8;
                    int cloc = nf*8 + (lane & 3)*2 + (q & 1);
                    int col = bn + wn*64 + cloc;
                    if (col < JJ) {
                        float p0 = acc[mi][nf][q];
                        float p1 = tb[rloc*64 + cloc];
                        out[(size_t)(bm + wm*32 + rloc)*JJ + col] =
                            p0 + (p1 - p0) * 0.015625f;
                    }
                }
    }
}

// ---------------------------------------------------------------------------
// image_logits[b, j] = max_p logits[b, p, j]
// ---------------------------------------------------------------------------
__global__ void imgmax_kernel(const float* __restrict__ logits, float* __restrict__ img) {
    int t = blockIdx.x * blockDim.x + threadIdx.x;
    if (t >= BB*JJ) return;
    int b = t / JJ, j = t % JJ;
    const float* p = logits + (size_t)b*PP*JJ + j;
    float m = -1e30f;
    for (int i = 0; i < PP; i++) m = fmaxf(m, p[(size_t)i*JJ]);
    img[(size_t)b*JJ + j] = m;
}

// ---------------------------------------------------------------------------
// class_logits[b, c] = sum_k img[b, c, k]*sw[c, k] / TEMP
// ---------------------------------------------------------------------------
__global__ void cls_kernel(const float* __restrict__ img, float* __restrict__ cls) {
    int t = blockIdx.x * blockDim.x + threadIdx.x;
    if (t >= BB*NCLS) return;
    int b = t / NCLS, c = t % NCLS;
    float s = 0.0f;
    #pragma unroll
    for (int k = 0; k < KP; k++) s += img[(size_t)b*JJ + c*KP + k] * g_sw[c*KP+k];
    cls[t] = s / 0.2f;
}

// ---------------------------------------------------------------------------
// Per-class: deterministic compaction + Sinkhorn + assignment + P_new
// ---------------------------------------------------------------------------
#define MAXN 1024
__global__ __launch_bounds__(256) void sinkhorn_kernel(
        const float* __restrict__ logits, const int* __restrict__ labels,
        const float* __restrict__ proto, const float* __restrict__ rpt,
        float* __restrict__ assign, float* __restrict__ pnew) {
    const int c = blockIdx.x;
    const int tid = threadIdx.x;
    const int lane = tid & 31, w = tid >> 5;

    __shared__ int   s_idx[MAXN];
    __shared__ float Q[KP][MAXN];
    __shared__ float red[256];
    __shared__ int   warp_cnt[8], warp_off[8];
    __shared__ int   s_n;

    if (tid == 0) s_n = 0;
    __syncthreads();

    for (int base = 0; base < NN; base += 256) {
        int n = base + tid;
        bool p = (labels[n] == c);
        unsigned bal = __ballot_sync(0xffffffffu, p);
        if (lane == 0) warp_cnt[w] = __popc(bal);
        __syncthreads();
        if (tid == 0) {
            int s = s_n;
            #pragma unroll
            for (int i = 0; i < 8; i++) { warp_off[i] = s; s += warp_cnt[i]; }
            s_n = s;
        }
        __syncthreads();
        if (p) {
            int pos = warp_off[w] + __popc(bal & ((1u << lane) - 1u));
            if (pos < MAXN) s_idx[pos] = n;
        }
        __syncthreads();
    }
    const int Nc = min(s_n, MAXN);

    if (Nc == 0) {
        for (int x = tid; x < KP*DD; x += 256)
            pnew[(size_t)c*KP*DD + x] = proto[(size_t)c*KP*DD + x];
        return;
    }

    for (int i = tid; i < Nc; i += 256) {
        const float* lp = logits + (size_t)s_idx[i]*JJ + c*KP;
        #pragma unroll
        for (int k = 0; k < KP; k++) Q[k][i] = expf(lp[k] * 20.0f);
    }
    __syncthreads();

    float s = 0.0f;
    for (int k = 0; k < KP; k++)
        for (int i = tid; i < Nc; i += 256) s += Q[k][i];
    red[tid] = s; __syncthreads();
    for (int o = 128; o > 0; o >>= 1) { if (tid < o) red[tid] += red[tid+o]; __syncthreads(); }
    float tot = red[0];
    __syncthreads();
    float dTot = (tot > 0.0f) ? tot : 1.0f;
    for (int k = 0; k < KP; k++)
        for (int i = tid; i < Nc; i += 256) Q[k][i] /= dTot;
    __syncthreads();

    const float fNc = (float)Nc;
    for (int it = 0; it < 3; it++) {
        for (int k = 0; k < KP; k++) {
            float rs = 0.0f;
            for (int i = tid; i < Nc; i += 256) rs += Q[k][i];
            red[tid] = rs; __syncthreads();
            for (int o = 128; o > 0; o >>= 1) { if (tid < o) red[tid] += red[tid+o]; __syncthreads(); }
            float r = red[0];
            __syncthreads();
            float dr = (r > 0.0f) ? r : 1.0f;
            for (int i = tid; i < Nc; i += 256) Q[k][i] = Q[k][i] / dr / 5.0f;
            __syncthreads();
        }
        for (int i = tid; i < Nc; i += 256) {
            float cs = Q[0][i]+Q[1][i]+Q[2][i]+Q[3][i]+Q[4][i];
            float dc = (cs > 0.0f) ? cs : 1.0f;
            #pragma unroll
            for (int k = 0; k < KP; k++) Q[k][i] = Q[k][i] / dc / fNc;
        }
        __syncthreads();
    }
    for (int k = 0; k < KP; k++)
        for (int i = tid; i < Nc; i += 256) Q[k][i] *= fNc;
    __syncthreads();

    for (int i = tid; i < Nc; i += 256) {
        float best = Q[0][i]; int ba = 0;
        #pragma unroll
        for (int k = 1; k < KP; k++) if (Q[k][i] > best) { best = Q[k][i]; ba = k; }
        assign[s_idx[i]] = (float)(c*KP + ba);
    }
    __syncthreads();

    for (int i = tid; i < Nc; i += 256) {
        float inv = g_inv[s_idx[i]];
        #pragma unroll
        for (int k = 0; k < KP; k++) Q[k][i] *= inv;
    }
    __syncthreads();

    const int d0 = tid * 3;
    float acc[KP][3];
    #pragma unroll
    for (int k = 0; k < KP; k++) { acc[k][0]=0.f; acc[k][1]=0.f; acc[k][2]=0.f; }
    for (int i = 0; i < Nc; i++) {
        const float* xp = rpt + (size_t)s_idx[i]*DD + d0;
        float x0 = xp[0], x1 = xp[1], x2 = xp[2];
        #pragma unroll
        for (int k = 0; k < KP; k++) {
            float q = Q[k][i];
            acc[k][0] = fmaf(q, x0, acc[k][0]);
            acc[k][1] = fmaf(q, x1, acc[k][1]);
            acc[k][2] = fmaf(q, x2, acc[k][2]);
        }
    }
    const float g = 0.999f, og = 1.0f - 0.999f;
    #pragma unroll
    for (int k = 0; k < KP; k++) {
        size_t basep = ((size_t)c*KP + k)*DD + d0;
        #pragma unroll
        for (int j = 0; j < 3; j++)
            pnew[basep + j] = g * proto[basep + j] + og * acc[k][j];
    }
}

// ---------------------------------------------------------------------------
extern "C" void kernel_launch(void* const* d_in, const int* in_sizes, int n_in,
                              void* d_out, int out_size) {
    const float* pt    = (const float*)d_in[0];
    const float* rpt   = (const float*)d_in[1];
    const float* proto = (const float*)d_in[2];
    const float* sa    = (const float*)d_in[3];
    const int*   lbl   = (const int*)  d_in[4];
    float* out = (float*)d_out;

    cudaFuncSetAttribute(gemm_mma_kernel,
                         cudaFuncAttributeMaxDynamicSharedMemorySize, SMEM_GEMM);

    pad_kernel<<<1, 32>>>();                              // keeps ncu window on GEMM
    norm_kernel<<<(2*NN + JPAD + 7)/8, 256>>>(pt, rpt, proto);
    sw_kernel<<<1, 256>>>(sa);
    {
        dim3 grid(NN/128, JPAD/128);   // 98 x 8
        gemm_mma_kernel<<<grid, 512, SMEM_GEMM>>>(out + OFF_LOGITS);
    }
    imgmax_kernel<<<(BB*JJ + 255)/256, 256>>>(out + OFF_LOGITS, out + OFF_IMG);
    cls_kernel<<<(BB*NCLS + 255)/256, 256>>>(out + OFF_IMG, out + OFF_CLS);
    sinkhorn_kernel<<<CC, 256>>>(out + OFF_LOGITS, lbl, proto, rpt,
                                 out + OFF_ASGN, out + OFF_PNEW);
}